// round 1
// baseline (speedup 1.0000x reference)
#include <cuda_runtime.h>

// Problem constants
#define B_ROWS 64
#define N_COLS 262144
#define N4 (N_COLS / 4)                 // 65536 float4 per row
#define THREADS 256
#define V4_PER_THREAD 2                 // 8 elements per thread per array
#define ELEMS_PER_BLOCK (THREADS * V4_PER_THREAD * 4)   // 2048
#define BLOCKS_PER_ROW (N_COLS / ELEMS_PER_BLOCK)       // 128

// Scratch: per-row [sum_t, sum(t*log p), sum((1-t)*log(1-p))], accumulated in double
__device__ double g_acc[B_ROWS * 3];

__global__ void zero_kernel() {
    int i = threadIdx.x;
    if (i < B_ROWS * 3) g_acc[i] = 0.0;
}

__global__ __launch_bounds__(THREADS) void bce_kernel(
    const float4* __restrict__ p4, const float4* __restrict__ t4) {
    const int row = blockIdx.y;
    // contiguous chunk of this row
    const long base = (long)row * N4 + (long)blockIdx.x * (THREADS * V4_PER_THREAD)
                      + threadIdx.x;

    // Front-batch all loads for MLP
    float4 pv[V4_PER_THREAD], tv[V4_PER_THREAD];
#pragma unroll
    for (int v = 0; v < V4_PER_THREAD; v++) {
        pv[v] = p4[base + (long)v * THREADS];
        tv[v] = t4[base + (long)v * THREADS];
    }

    float st = 0.f, s1 = 0.f, s2 = 0.f;
#pragma unroll
    for (int v = 0; v < V4_PER_THREAD; v++) {
        const float pe[4] = {pv[v].x, pv[v].y, pv[v].z, pv[v].w};
        const float te[4] = {tv[v].x, tv[v].y, tv[v].z, tv[v].w};
#pragma unroll
        for (int e = 0; e < 4; e++) {
            float lp = __logf(pe[e]);
            float lq = __logf(1.0f - pe[e]);
            st += te[e];
            s1 = fmaf(te[e], lp, s1);
            s2 += lq - te[e] * lq;      // (1-t)*log(1-p)
        }
    }

    // warp reduce
#pragma unroll
    for (int o = 16; o > 0; o >>= 1) {
        st += __shfl_down_sync(0xFFFFFFFFu, st, o);
        s1 += __shfl_down_sync(0xFFFFFFFFu, s1, o);
        s2 += __shfl_down_sync(0xFFFFFFFFu, s2, o);
    }

    __shared__ float sh_st[THREADS / 32], sh_s1[THREADS / 32], sh_s2[THREADS / 32];
    const int warp = threadIdx.x >> 5;
    const int lane = threadIdx.x & 31;
    if (lane == 0) { sh_st[warp] = st; sh_s1[warp] = s1; sh_s2[warp] = s2; }
    __syncthreads();

    if (warp == 0) {
        const int nw = THREADS / 32;
        float a = (lane < nw) ? sh_st[lane] : 0.f;
        float b = (lane < nw) ? sh_s1[lane] : 0.f;
        float c = (lane < nw) ? sh_s2[lane] : 0.f;
#pragma unroll
        for (int o = 4; o > 0; o >>= 1) {
            a += __shfl_down_sync(0xFFFFFFFFu, a, o);
            b += __shfl_down_sync(0xFFFFFFFFu, b, o);
            c += __shfl_down_sync(0xFFFFFFFFu, c, o);
        }
        if (lane == 0) {
            atomicAdd(&g_acc[row * 3 + 0], (double)a);
            atomicAdd(&g_acc[row * 3 + 1], (double)b);
            atomicAdd(&g_acc[row * 3 + 2], (double)c);
        }
    }
}

__global__ void finalize_kernel(float* __restrict__ out) {
    const int i = threadIdx.x;   // 64 threads, one per row
    double contrib = 0.0;
    if (i < B_ROWS) {
        double st = g_acc[3 * i + 0];
        double s1 = g_acc[3 * i + 1];
        double s2 = g_acc[3 * i + 2];
        double beta = 1.0 - st / (double)N_COLS;
        contrib = beta * s1 + (1.0 - beta) * s2;
    }
#pragma unroll
    for (int o = 16; o > 0; o >>= 1)
        contrib += __shfl_down_sync(0xFFFFFFFFu, contrib, o);

    __shared__ double sh[2];
    if ((i & 31) == 0) sh[i >> 5] = contrib;
    __syncthreads();
    if (i == 0) out[0] = (float)(-(sh[0] + sh[1]));
}

extern "C" void kernel_launch(void* const* d_in, const int* in_sizes, int n_in,
                              void* d_out, int out_size) {
    const float4* p = (const float4*)d_in[0];  // input (probabilities)
    const float4* t = (const float4*)d_in[1];  // target
    float* out = (float*)d_out;

    zero_kernel<<<1, 256>>>();
    dim3 grid(BLOCKS_PER_ROW, B_ROWS);
    bce_kernel<<<grid, THREADS>>>(p, t);
    finalize_kernel<<<1, 64>>>(out);
}

// round 2
// speedup vs baseline: 1.0647x; 1.0647x over previous
#include <cuda_runtime.h>

// Problem constants
#define B_ROWS 64
#define N_COLS 262144
#define N4 (N_COLS / 4)                 // 65536 float4 per row
#define THREADS 256
#define V4_PER_THREAD 4                 // 16 elements per thread per array
#define F4_PER_BLOCK (THREADS * V4_PER_THREAD)          // 1024 float4
#define BLOCKS_PER_ROW (N4 / F4_PER_BLOCK)              // 64
#define TOTAL_BLOCKS (B_ROWS * BLOCKS_PER_ROW)          // 4096

// Deterministic scratch: every slot overwritten unconditionally every launch,
// so no zeroing kernel is needed (graph-replay safe).
__device__ float g_st[TOTAL_BLOCKS];   // sum(t)
__device__ float g_s1[TOTAL_BLOCKS];   // sum(t * log2(p))
__device__ float g_s2[TOTAL_BLOCKS];   // sum((1-t) * log2(1-p))

__global__ __launch_bounds__(THREADS) void bce_kernel(
    const float4* __restrict__ p4, const float4* __restrict__ t4) {
    const int row = blockIdx.y;
    const int chunk = blockIdx.x;
    const long base = (long)row * N4 + (long)chunk * F4_PER_BLOCK + threadIdx.x;

    // Front-batch all loads for MLP
    float4 pv[V4_PER_THREAD], tv[V4_PER_THREAD];
#pragma unroll
    for (int v = 0; v < V4_PER_THREAD; v++) {
        pv[v] = p4[base + (long)v * THREADS];
        tv[v] = t4[base + (long)v * THREADS];
    }

    float st = 0.f, s1 = 0.f, s2 = 0.f;
#pragma unroll
    for (int v = 0; v < V4_PER_THREAD; v++) {
        const float pe[4] = {pv[v].x, pv[v].y, pv[v].z, pv[v].w};
        const float te[4] = {tv[v].x, tv[v].y, tv[v].z, tv[v].w};
#pragma unroll
        for (int e = 0; e < 4; e++) {
            float lp = __log2f(pe[e]);          // bare LG2, scaled by ln2 in finalize
            float lq = __log2f(1.0f - pe[e]);
            st += te[e];
            s1 = fmaf(te[e], lp, s1);
            s2 += lq - te[e] * lq;              // (1-t)*log2(1-p)
        }
    }

    // warp reduce
#pragma unroll
    for (int o = 16; o > 0; o >>= 1) {
        st += __shfl_down_sync(0xFFFFFFFFu, st, o);
        s1 += __shfl_down_sync(0xFFFFFFFFu, s1, o);
        s2 += __shfl_down_sync(0xFFFFFFFFu, s2, o);
    }

    __shared__ float sh_st[THREADS / 32], sh_s1[THREADS / 32], sh_s2[THREADS / 32];
    const int warp = threadIdx.x >> 5;
    const int lane = threadIdx.x & 31;
    if (lane == 0) { sh_st[warp] = st; sh_s1[warp] = s1; sh_s2[warp] = s2; }
    __syncthreads();

    if (warp == 0) {
        const int nw = THREADS / 32;
        float a = (lane < nw) ? sh_st[lane] : 0.f;
        float b = (lane < nw) ? sh_s1[lane] : 0.f;
        float c = (lane < nw) ? sh_s2[lane] : 0.f;
#pragma unroll
        for (int o = 4; o > 0; o >>= 1) {
            a += __shfl_down_sync(0xFFFFFFFFu, a, o);
            b += __shfl_down_sync(0xFFFFFFFFu, b, o);
            c += __shfl_down_sync(0xFFFFFFFFu, c, o);
        }
        if (lane == 0) {
            const int idx = row * BLOCKS_PER_ROW + chunk;
            g_st[idx] = a;
            g_s1[idx] = b;
            g_s2[idx] = c;
        }
    }
}

// 1 block, 1024 threads: 16 threads per row x 64 rows.
// Each 16-lane subgroup reduces its row's 64 partials (4 per thread),
// then per-row beta combine, then block-wide double reduction.
__global__ __launch_bounds__(1024) void finalize_kernel(float* __restrict__ out) {
    const int tid = threadIdx.x;
    const int row = tid >> 4;          // 0..63
    const int sub = tid & 15;          // 0..15

    float st = 0.f, s1 = 0.f, s2 = 0.f;
#pragma unroll
    for (int k = 0; k < BLOCKS_PER_ROW / 16; k++) {   // 4 iters
        const int idx = row * BLOCKS_PER_ROW + sub + k * 16;
        st += g_st[idx];
        s1 += g_s1[idx];
        s2 += g_s2[idx];
    }
    // reduce within 16-lane subgroup
#pragma unroll
    for (int o = 8; o > 0; o >>= 1) {
        st += __shfl_down_sync(0xFFFFFFFFu, st, o, 16);
        s1 += __shfl_down_sync(0xFFFFFFFFu, s1, o, 16);
        s2 += __shfl_down_sync(0xFFFFFFFFu, s2, o, 16);
    }

    __shared__ double sh_row[B_ROWS];
    if (sub == 0) {
        const double LN2 = 0.6931471805599453;
        double beta = 1.0 - (double)st / (double)N_COLS;
        sh_row[row] = (beta * (double)s1 + (1.0 - beta) * (double)s2) * LN2;
    }
    __syncthreads();

    // reduce 64 row contributions with warps 0-1
    if (tid < 64) {
        double c = sh_row[tid];
#pragma unroll
        for (int o = 16; o > 0; o >>= 1)
            c += __shfl_down_sync(0xFFFFFFFFu, c, o);
        __shared__ double sh2[2];
        if ((tid & 31) == 0) sh2[tid >> 5] = c;
        __syncthreads();
        if (tid == 0) out[0] = (float)(-(sh2[0] + sh2[1]));
    }
}

extern "C" void kernel_launch(void* const* d_in, const int* in_sizes, int n_in,
                              void* d_out, int out_size) {
    const float4* p = (const float4*)d_in[0];  // input (probabilities)
    const float4* t = (const float4*)d_in[1];  // target
    float* out = (float*)d_out;

    dim3 grid(BLOCKS_PER_ROW, B_ROWS);
    bce_kernel<<<grid, THREADS>>>(p, t);
    finalize_kernel<<<1, 1024>>>(out);
}